// round 11
// baseline (speedup 1.0000x reference)
#include <cuda_runtime.h>
#include <math.h>

#define BATCH  16
#define CC     64
#define MM     4096
#define LDS    68     // smem row stride (words); 68 % 32 == 4 -> conflict-free frags
#define LDP    68
#define NF4    (BATCH * CC * MM / 4)    // 1048576 float4 total
#define DSMEM  (4 * 64 * LDP * 4)       // 69632 bytes dynamic smem

// Deterministic scratch + sequencing state (all zero-initialized at load).
__device__ float g_part[BATCH * 32 * CC * CC];   // up to 32 partials/batch
__device__ float g_rspart[BATCH * 32 * CC];
__device__ float g_scale[BATCH * CC];
__device__ int   g_cnt1[BATCH];
__device__ int   g_flag[BATCH];
__device__ int   g_done;

__device__ __forceinline__ unsigned cvt_tf32(float f) {
    unsigned r; asm("cvt.rna.tf32.f32 %0, %1;" : "=r"(r) : "f"(f)); return r;
}
__device__ __forceinline__ float tf32f(float f) {
    return __uint_as_float(cvt_tf32(f));
}
__device__ __forceinline__ void mma_tf32(float c[4], unsigned a0, unsigned a1,
                                         unsigned a2, unsigned a3,
                                         unsigned b0, unsigned b1) {
    asm("mma.sync.aligned.m16n8k8.row.col.f32.tf32.tf32.f32 "
        "{%0,%1,%2,%3},{%4,%5,%6,%7},{%8,%9},{%0,%1,%2,%3};"
        : "+f"(c[0]), "+f"(c[1]), "+f"(c[2]), "+f"(c[3])
        : "r"(a0), "r"(a1), "r"(a2), "r"(a3), "r"(b0), "r"(b1));
}

// 64x64x64 matmul via tf32 mma.sync on pre-rounded tf32-valued fp32 in smem.
// C = A@B (mode 0) or 0.5*(3I - A@B) (mode 1). Requires SYMMETRIC B (all NS
// matrices are polynomials of the symmetric A). Whole 256-thread block.
__device__ __forceinline__ void mm64t(float* __restrict__ C, const float* __restrict__ A,
                                      const float* __restrict__ B, int w, int lane, int mode) {
    const int m0 = 16 * (w & 3);
    const int n0b = 32 * (w >> 2);
    const int g = lane >> 2, tg = lane & 3;
    const unsigned* Au = (const unsigned*)A;
    const unsigned* Bu = (const unsigned*)B;

    float c[4][4];
#pragma unroll
    for (int j = 0; j < 4; j++)
#pragma unroll
        for (int q = 0; q < 4; q++) c[j][q] = 0.f;

#pragma unroll
    for (int k0 = 0; k0 < 64; k0 += 8) {
        unsigned a0 = Au[(m0 + g) * LDP + k0 + tg];
        unsigned a1 = Au[(m0 + g + 8) * LDP + k0 + tg];
        unsigned a2 = Au[(m0 + g) * LDP + k0 + tg + 4];
        unsigned a3 = Au[(m0 + g + 8) * LDP + k0 + tg + 4];
#pragma unroll
        for (int j = 0; j < 4; j++) {
            int n0 = n0b + 8 * j;
            unsigned b0 = Bu[(n0 + g) * LDP + k0 + tg];
            unsigned b1 = Bu[(n0 + g) * LDP + k0 + tg + 4];
            mma_tf32(c[j], a0, a1, a2, a3, b0, b1);
        }
    }
    __syncthreads();
#pragma unroll
    for (int j = 0; j < 4; j++) {
        int col = n0b + 8 * j + 2 * tg;
        int r0 = m0 + g, r1 = m0 + g + 8;
        float v0 = c[j][0], v1 = c[j][1], v2 = c[j][2], v3 = c[j][3];
        if (mode) {
            v0 = 0.5f * (((r0 == col)     ? 3.f : 0.f) - v0);
            v1 = 0.5f * (((r0 == col + 1) ? 3.f : 0.f) - v1);
            v2 = 0.5f * (((r1 == col)     ? 3.f : 0.f) - v2);
            v3 = 0.5f * (((r1 == col + 1) ? 3.f : 0.f) - v3);
        }
        *(float2*)&C[r0 * LDP + col] = make_float2(tf32f(v0), tf32f(v1));
        *(float2*)&C[r1 * LDP + col] = make_float2(tf32f(v2), tf32f(v3));
    }
    __syncthreads();
}

// ---------------------------------------------------------------------------
// Fused persistent kernel. grid = 16*gpb blocks (co-resident by construction),
// 256 threads, DSMEM dynamic smem.
// Phase 1: cov partials (each block: tiles slot, slot+gpb, ... of its batch).
// Phase 2: last-arriving block per batch reduces partials + runs NS -> flag.
// Phase 3: every block scales its 1/G slice of x (waits on <=2 batch flags).
// ---------------------------------------------------------------------------
__global__ __launch_bounds__(256, 3) void fused_kernel(
    const float* __restrict__ x,
    const float* __restrict__ w1, const float* __restrict__ b1,
    const float* __restrict__ w2, const float* __restrict__ b2,
    float* __restrict__ out)
{
    extern __shared__ float sm[];
    __shared__ __align__(16) float svec[64];
    __shared__ float vvec[64];
    __shared__ float red[8];
    __shared__ float snorm;
    __shared__ int s_last;

    const int t = threadIdx.x;
    const int lane = t & 31, w = t >> 5;
    const int gpb = gridDim.x >> 4;          // blocks per batch
    const int blk = blockIdx.x;
    const int b = blk / gpb;
    const int slot = blk - b * gpb;

    // ======================= Phase 1: cov partials =======================
    {
        unsigned* buf = (unsigned*)sm;              // 64*LDS words
        const int m0 = 16 * (w & 3);
        const int n0base = 32 * (w >> 2);
        const int g = lane >> 2, tg = lane & 3;
        const int lrow = t >> 4, lcg = t & 15;
        const float* xb0 = x + (size_t)b * CC * MM;

        float c[4][4];
#pragma unroll
        for (int j = 0; j < 4; j++)
#pragma unroll
            for (int q = 0; q < 4; q++) c[j][q] = 0.f;
        float rs[4] = {0.f, 0.f, 0.f, 0.f};

        for (int tile = slot; tile < 64; tile += gpb) {
            const float* xb = xb0 + tile * 64;
            // LDGs issued before the sync so they overlap the previous mma.
            float4 v[4];
#pragma unroll
            for (int j = 0; j < 4; j++)
                v[j] = *(const float4*)&xb[(size_t)(j * 16 + lrow) * MM + 4 * lcg];
            __syncthreads();   // previous mma done reading buf
#pragma unroll
            for (int j = 0; j < 4; j++) {
                int row = j * 16 + lrow;
                rs[j] += (v[j].x + v[j].y) + (v[j].z + v[j].w);
                uint4 u;
                u.x = cvt_tf32(v[j].x); u.y = cvt_tf32(v[j].y);
                u.z = cvt_tf32(v[j].z); u.w = cvt_tf32(v[j].w);
                *(uint4*)&buf[row * LDS + 4 * lcg] = u;
            }
            __syncthreads();
#pragma unroll
            for (int k0 = 0; k0 < 64; k0 += 8) {
                unsigned a0 = buf[(m0 + g) * LDS + k0 + tg];
                unsigned a1 = buf[(m0 + g + 8) * LDS + k0 + tg];
                unsigned a2 = buf[(m0 + g) * LDS + k0 + tg + 4];
                unsigned a3 = buf[(m0 + g + 8) * LDS + k0 + tg + 4];
#pragma unroll
                for (int j = 0; j < 4; j++) {
                    int n0 = n0base + 8 * j;
                    unsigned b0 = buf[(n0 + g) * LDS + k0 + tg];
                    unsigned b1 = buf[(n0 + g) * LDS + k0 + tg + 4];
                    mma_tf32(c[j], a0, a1, a2, a3, b0, b1);
                }
            }
        }

        // Write this block's partial Gram.
        float* P = g_part + (((size_t)(b * 32 + slot)) << 12);
#pragma unroll
        for (int j = 0; j < 4; j++) {
            int row = m0 + g, col = n0base + 8 * j + 2 * tg;
            *(float2*)&P[row * 64 + col]       = make_float2(c[j][0], c[j][1]);
            *(float2*)&P[(row + 8) * 64 + col] = make_float2(c[j][2], c[j][3]);
        }
        // Row sums (scratch region after buf: word offset 64*LDS).
        float* rsm = sm + 64 * LDS;
        __syncthreads();
#pragma unroll
        for (int j = 0; j < 4; j++)
            rsm[(j * 16 + lrow) * 17 + lcg] = rs[j];
        __syncthreads();
        if (t < 64) {
            float s = 0.f;
#pragma unroll
            for (int i = 0; i < 16; i++) s += rsm[t * 17 + i];
            g_rspart[(b * 32 + slot) * 64 + t] = s;
        }
    }

    // Publish partials; elect the last-arriving block of this batch for NS.
    __threadfence();
    __syncthreads();
    if (t == 0) s_last = (atomicAdd(&g_cnt1[b], 1) == gpb - 1) ? 1 : 0;
    __syncthreads();
    __threadfence();   // acquire side for the electee's upcoming reads

    // ======================= Phase 2: reduce + NS =======================
    if (s_last) {
        if (t == 0) atomicExch(&g_cnt1[b], 0);   // reset for next replay

        float* S0 = sm;
        float* S1 = sm + 64 * LDP;
        float* S2 = sm + 2 * 64 * LDP;
        float* S3 = sm + 3 * 64 * LDP;
        const float invM = 1.0f / (float)MM;
        const float invM2 = invM * invM;

        // total row sums
        if (t < 64) {
            float s = 0.f;
            for (int sp = 0; sp < gpb; sp++) s += g_rspart[(b * 32 + sp) * 64 + t];
            svec[t] = s;
        }
        __syncthreads();

        // cov = Sxx/M - s s^T/M^2 (Sxx reduced inline, float4); normA = sum
        const float4* P4 = (const float4*)(g_part + ((size_t)(b * 32) << 12));
        float lsum = 0.f;
#pragma unroll
        for (int e = 0; e < 4; e++) {
            int q = e * 256 + t;            // float4 index 0..1023
            int i = q >> 4;                 // row
            int j0 = (q & 15) * 4;          // col base
            float4 s = make_float4(0.f, 0.f, 0.f, 0.f);
            for (int sp = 0; sp < gpb; sp++) {
                float4 p = P4[sp * 1024 + q];
                s.x += p.x; s.y += p.y; s.z += p.z; s.w += p.w;
            }
            float4 sj = *(const float4*)&svec[j0];
            float si = svec[i];
            float c0 = invM * s.x - invM2 * si * sj.x;
            float c1 = invM * s.y - invM2 * si * sj.y;
            float c2 = invM * s.z - invM2 * si * sj.z;
            float c3 = invM * s.w - invM2 * si * sj.w;
            S0[i * LDP + j0 + 0] = c0;
            S0[i * LDP + j0 + 1] = c1;
            S0[i * LDP + j0 + 2] = c2;
            S0[i * LDP + j0 + 3] = c3;
            lsum += (c0 + c1) + (c2 + c3);
        }
#pragma unroll
        for (int o = 16; o; o >>= 1) lsum += __shfl_xor_sync(0xffffffffu, lsum, o);
        if ((t & 31) == 0) red[t >> 5] = lsum;
        __syncthreads();
        if (t == 0) { float s = 0.f; for (int q = 0; q < 8; q++) s += red[q]; snorm = s; }
        __syncthreads();

        const float invN = 1.f / snorm;
#pragma unroll
        for (int e = 0; e < 16; e++) {
            int idx = e * 256 + t;
            int i = idx >> 6, j = idx & 63;
            float a = S0[i * LDP + j] * invN;
            S0[i * LDP + j] = tf32f(a);
            float zy = 0.5f * (((i == j) ? 3.f : 0.f) - a);
            float zyt = tf32f(zy);
            S3[i * LDP + j] = zyt;   // ZY
            S2[i * LDP + j] = zyt;   // Z = ZY
        }
        __syncthreads();

        mm64t(S1, S0, S3, w, lane, 0);   // Y = A @ ZY

        float* pY = S1; float* pZ = S2; float* pT = S0; float* pU = S3;
        for (int it = 0; it < 3; it++) {
            mm64t(pT, pZ, pY, w, lane, 1);   // ZYnew = 0.5(3I - Z@Y)
            mm64t(pU, pY, pT, w, lane, 0);   // Ynew = Y @ ZYnew
            mm64t(pY, pT, pZ, w, lane, 0);   // Znew = ZYnew @ Z
            float* oY = pY; float* oZ = pZ; float* oT = pT; float* oU = pU;
            pY = oU; pZ = oY; pT = oT; pU = oZ;
        }

        // Stage conv center taps into the two dead smem matrices.
        float* W1 = pT;
        float* W2 = pU;
#pragma unroll
        for (int e = 0; e < 16; e++) {
            int n = e * 256 + t;
            W1[n] = w1[n * 9 + 4];
            W2[n] = w2[n * 9 + 4];
        }
        __syncthreads();
        // y_vec = (0.5/64)*sqrt(normA) * (3u - (u^T Z) Y), u = colsum(Y)
        if (t < 64) {
            float u = 0.f;
            for (int i = 0; i < 64; i++) u += pY[i * LDP + t];
            svec[t] = u;
        }
        __syncthreads();
        if (t < 64) {
            float vv = 0.f;
            for (int i = 0; i < 64; i++) vv += svec[i] * pZ[i * LDP + t];
            vvec[t] = vv;
        }
        __syncthreads();
        if (t < 64) {
            float wv = 0.f;
            for (int k = 0; k < 64; k++) wv += vvec[k] * pY[k * LDP + t];
            float cc = (0.5f / 64.f) * sqrtf(snorm);
            svec[t] = cc * (3.f * svec[t] - wv);
        }
        __syncthreads();
        if (t < 64) {
            float a = b1[t];
            for (int i = 0; i < 64; i++) a += W1[t * 64 + i] * svec[i];
            vvec[t] = fmaxf(a, 0.f);
        }
        __syncthreads();
        if (t < 64) {
            float a = b2[t];
            for (int i = 0; i < 64; i++) a += W2[t * 64 + i] * vvec[i];
            g_scale[b * 64 + t] = 1.f / (1.f + expf(-a));
        }
        __threadfence();
        __syncthreads();
        if (t == 0) atomicExch(&g_flag[b], 1);
    }

    // ======================= Phase 3: scale =======================
    {
        const int G = gridDim.x;
        const int Q = (NF4 + G - 1) / G;
        const int start = blk * Q;
        const int end = (start + Q < NF4) ? (start + Q) : NF4;
        if (start < end) {
            int b0 = start >> 16, b1 = (end - 1) >> 16;   // 65536 float4 per batch
            if (t == 0) {
                for (int bb = b0; bb <= b1; bb++)
                    while (atomicAdd(&g_flag[bb], 0) == 0) __nanosleep(200);
            }
            __syncthreads();
            __threadfence();
            const float4* x4 = (const float4*)x;
            float4* out4 = (float4*)out;
            for (int i = start + t; i < end; i += 256) {
                float s = g_scale[i >> 10];   // 1024 float4 per channel
                float4 v = __ldg(&x4[i]);
                v.x *= s; v.y *= s; v.z *= s; v.w *= s;
                __stcs(&out4[i], v);
            }
        }
    }

    // Epilogue: global-last block resets flags for the next replay
    // (runs only after ALL blocks finished their flag reads + scaling).
    __threadfence();
    __syncthreads();
    if (t == 0) {
        if (atomicAdd(&g_done, 1) == gridDim.x - 1) {
            for (int i = 0; i < BATCH; i++) atomicExch(&g_flag[i], 0);
            atomicExch(&g_done, 0);
        }
    }
}

extern "C" void kernel_launch(void* const* d_in, const int* in_sizes, int n_in,
                              void* d_out, int out_size) {
    const float* x  = (const float*)d_in[0];
    const float* w1 = (const float*)d_in[1];
    const float* b1 = (const float*)d_in[2];
    const float* w2 = (const float*)d_in[3];
    const float* b2 = (const float*)d_in[4];
    float* out = (float*)d_out;

    (void)in_sizes; (void)n_in; (void)out_size;

    cudaFuncSetAttribute(fused_kernel, cudaFuncAttributeMaxDynamicSharedMemorySize, DSMEM);

    // Size the grid so ALL blocks are co-resident (spin-waits are safe).
    int dev = 0;
    cudaGetDevice(&dev);
    int nsm = 148;
    cudaDeviceGetAttribute(&nsm, cudaDevAttrMultiProcessorCount, dev);
    int occ = 1;
    cudaOccupancyMaxActiveBlocksPerMultiprocessor(&occ, fused_kernel, 256, DSMEM);
    int gpb = (occ * nsm) / 16;
    if (gpb > 27) gpb = 27;     // >27 gives no further tile-split benefit (64 tiles)
    if (gpb < 1) gpb = 1;

    fused_kernel<<<16 * gpb, 256, DSMEM>>>(x, w1, b1, w2, b2, out);
}

// round 12
// speedup vs baseline: 1.4327x; 1.4327x over previous
#include <cuda_runtime.h>
#include <math.h>

#define BATCH  16
#define CC     64
#define MM     4096
#define NSPLIT 32     // 128-col chunk per cov block -> 512 blocks
#define CHUNK  128
#define LDS    68     // smem row stride (words); 68 % 32 == 4 -> conflict-free frags
#define LDP    68
#define NF4    (BATCH * CC * MM / 4)    // 1048576 float4 total
#define NSCALE 428                      // scale blocks in tail kernel
#define SLICE  2450                     // float4 per scale block (428*2450 >= NF4)
#define DSMEM  (4 * 64 * LDP * 4)       // 69632 bytes dynamic smem (tail kernel)

// Deterministic scratch + sequencing state (zero-initialized at load).
__device__ float g_part[BATCH * NSPLIT * CC * CC];   // 8 MB partial Grams
__device__ float g_rspart[BATCH * NSPLIT * CC];
__device__ float g_scale[BATCH * CC];
__device__ int   g_flag[BATCH];
__device__ int   g_done;

__device__ __forceinline__ unsigned cvt_tf32(float f) {
    unsigned r; asm("cvt.rna.tf32.f32 %0, %1;" : "=r"(r) : "f"(f)); return r;
}
__device__ __forceinline__ float tf32f(float f) {
    return __uint_as_float(cvt_tf32(f));
}
__device__ __forceinline__ void mma_tf32(float c[4], unsigned a0, unsigned a1,
                                         unsigned a2, unsigned a3,
                                         unsigned b0, unsigned b1) {
    asm("mma.sync.aligned.m16n8k8.row.col.f32.tf32.tf32.f32 "
        "{%0,%1,%2,%3},{%4,%5,%6,%7},{%8,%9},{%0,%1,%2,%3};"
        : "+f"(c[0]), "+f"(c[1]), "+f"(c[2]), "+f"(c[3])
        : "r"(a0), "r"(a1), "r"(a2), "r"(a3), "r"(b0), "r"(b1));
}

// ---------------------------------------------------------------------------
// Kernel 1: partial X·X^T per (batch, 128-col chunk) via tf32 mma.sync,
// + fp32 partial row sums. grid (NSPLIT, BATCH) = 512 blocks, 256 threads.
// (R8-proven version.)
// ---------------------------------------------------------------------------
__global__ __launch_bounds__(256) void cov_kernel(const float* __restrict__ x) {
    __shared__ unsigned buf[64 * LDS];
    const int split = blockIdx.x, b = blockIdx.y;
    const int t = threadIdx.x;
    const int lane = t & 31, w = t >> 5;
    const int m0 = 16 * (w & 3);
    const int n0base = 32 * (w >> 2);
    const int g = lane >> 2, tg = lane & 3;
    const int lrow = t >> 4, lcg = t & 15;
    const float* xb = x + (size_t)b * CC * MM + (size_t)split * CHUNK;

    float c[4][4];
#pragma unroll
    for (int j = 0; j < 4; j++)
#pragma unroll
        for (int q = 0; q < 4; q++) c[j][q] = 0.f;
    float rs[4] = {0.f, 0.f, 0.f, 0.f};

    for (int kb = 0; kb < CHUNK / 64; kb++) {
        __syncthreads();
#pragma unroll
        for (int j = 0; j < 4; j++) {
            int row = j * 16 + lrow;
            float4 v = *(const float4*)&xb[(size_t)row * MM + kb * 64 + 4 * lcg];
            rs[j] += (v.x + v.y) + (v.z + v.w);
            uint4 u;
            u.x = cvt_tf32(v.x); u.y = cvt_tf32(v.y);
            u.z = cvt_tf32(v.z); u.w = cvt_tf32(v.w);
            *(uint4*)&buf[row * LDS + 4 * lcg] = u;
        }
        __syncthreads();
#pragma unroll
        for (int k0 = 0; k0 < 64; k0 += 8) {
            unsigned a0 = buf[(m0 + g) * LDS + k0 + tg];
            unsigned a1 = buf[(m0 + g + 8) * LDS + k0 + tg];
            unsigned a2 = buf[(m0 + g) * LDS + k0 + tg + 4];
            unsigned a3 = buf[(m0 + g + 8) * LDS + k0 + tg + 4];
#pragma unroll
            for (int j = 0; j < 4; j++) {
                int n0 = n0base + 8 * j;
                unsigned b0 = buf[(n0 + g) * LDS + k0 + tg];
                unsigned b1 = buf[(n0 + g) * LDS + k0 + tg + 4];
                mma_tf32(c[j], a0, a1, a2, a3, b0, b1);
            }
        }
    }

    float* P = g_part + (((size_t)(b * NSPLIT + split)) << 12);
#pragma unroll
    for (int j = 0; j < 4; j++) {
        int row = m0 + g, col = n0base + 8 * j + 2 * tg;
        *(float2*)&P[row * 64 + col]       = make_float2(c[j][0], c[j][1]);
        *(float2*)&P[(row + 8) * 64 + col] = make_float2(c[j][2], c[j][3]);
    }

    __syncthreads();
    float* rsm = (float*)buf;
#pragma unroll
    for (int j = 0; j < 4; j++)
        rsm[(j * 16 + lrow) * 17 + lcg] = rs[j];
    __syncthreads();
    if (t < 64) {
        float s = 0.f;
#pragma unroll
        for (int i = 0; i < 16; i++) s += rsm[t * 17 + i];
        g_rspart[(b * NSPLIT + split) * 64 + t] = s;
    }
}

// ---------------------------------------------------------------------------
// 64x64x64 matmul via tf32 mma.sync on pre-rounded tf32-valued fp32 in smem.
// C = A@B (mode 0) or 0.5*(3I - A@B) (mode 1). Requires SYMMETRIC B.
// ---------------------------------------------------------------------------
__device__ __forceinline__ void mm64t(float* __restrict__ C, const float* __restrict__ A,
                                      const float* __restrict__ B, int w, int lane, int mode) {
    const int m0 = 16 * (w & 3);
    const int n0b = 32 * (w >> 2);
    const int g = lane >> 2, tg = lane & 3;
    const unsigned* Au = (const unsigned*)A;
    const unsigned* Bu = (const unsigned*)B;

    float c[4][4];
#pragma unroll
    for (int j = 0; j < 4; j++)
#pragma unroll
        for (int q = 0; q < 4; q++) c[j][q] = 0.f;

#pragma unroll
    for (int k0 = 0; k0 < 64; k0 += 8) {
        unsigned a0 = Au[(m0 + g) * LDP + k0 + tg];
        unsigned a1 = Au[(m0 + g + 8) * LDP + k0 + tg];
        unsigned a2 = Au[(m0 + g) * LDP + k0 + tg + 4];
        unsigned a3 = Au[(m0 + g + 8) * LDP + k0 + tg + 4];
#pragma unroll
        for (int j = 0; j < 4; j++) {
            int n0 = n0b + 8 * j;
            unsigned b0 = Bu[(n0 + g) * LDP + k0 + tg];
            unsigned b1 = Bu[(n0 + g) * LDP + k0 + tg + 4];
            mma_tf32(c[j], a0, a1, a2, a3, b0, b1);
        }
    }
    __syncthreads();
#pragma unroll
    for (int j = 0; j < 4; j++) {
        int col = n0b + 8 * j + 2 * tg;
        int r0 = m0 + g, r1 = m0 + g + 8;
        float v0 = c[j][0], v1 = c[j][1], v2 = c[j][2], v3 = c[j][3];
        if (mode) {
            v0 = 0.5f * (((r0 == col)     ? 3.f : 0.f) - v0);
            v1 = 0.5f * (((r0 == col + 1) ? 3.f : 0.f) - v1);
            v2 = 0.5f * (((r1 == col)     ? 3.f : 0.f) - v2);
            v3 = 0.5f * (((r1 == col + 1) ? 3.f : 0.f) - v3);
        }
        *(float2*)&C[r0 * LDP + col] = make_float2(tf32f(v0), tf32f(v1));
        *(float2*)&C[r1 * LDP + col] = make_float2(tf32f(v2), tf32f(v3));
    }
    __syncthreads();
}

// ---------------------------------------------------------------------------
// Kernel 2 (tail): 16 NS blocks + 428 scale blocks = 444 blocks (one wave).
// Blocks 0..15: inline reduce (float4) + NS + SE tail -> g_scale + flag.
//   They wait on NOTHING, and bid 0..15 guarantees wave-1 scheduling, so
//   scale-block spins always terminate (no co-residency assumption).
// Blocks 16..443: wait <=2 batch flags, then scale a contiguous slice of x.
// Flags reset by the globally-last block (replay-safe).
// ---------------------------------------------------------------------------
__global__ __launch_bounds__(256) void tail_kernel(
    const float* __restrict__ x,
    const float* __restrict__ w1, const float* __restrict__ b1,
    const float* __restrict__ w2, const float* __restrict__ b2,
    float* __restrict__ out)
{
    extern __shared__ float sm[];
    __shared__ __align__(16) float svec[64];
    __shared__ float vvec[64];
    __shared__ float red[8];
    __shared__ float snorm;

    const int blk = blockIdx.x;
    const int t = threadIdx.x;
    const int lane = t & 31, w = t >> 5;

    if (blk < BATCH) {
        // =================== NS block for batch b ===================
        const int b = blk;
        float* S0 = sm;
        float* S1 = sm + 64 * LDP;
        float* S2 = sm + 2 * 64 * LDP;
        float* S3 = sm + 3 * 64 * LDP;
        const float invM = 1.0f / (float)MM;
        const float invM2 = invM * invM;

        // total row sums
        if (t < 64) {
            float s = 0.f;
#pragma unroll
            for (int sp = 0; sp < NSPLIT; sp++) s += g_rspart[(b * NSPLIT + sp) * 64 + t];
            svec[t] = s;
        }
        __syncthreads();

        // cov = Sxx/M - s s^T/M^2 (Sxx reduced inline, float4 32-way MLP)
        const float4* P4 = (const float4*)(g_part + (((size_t)b * NSPLIT) << 12));
        float lsum = 0.f;
#pragma unroll
        for (int e = 0; e < 4; e++) {
            int q = e * 256 + t;            // float4 index 0..1023
            int i = q >> 4;                 // row
            int j0 = (q & 15) * 4;          // col base
            float4 s = make_float4(0.f, 0.f, 0.f, 0.f);
#pragma unroll 8
            for (int sp = 0; sp < NSPLIT; sp++) {
                float4 p = P4[sp * 1024 + q];
                s.x += p.x; s.y += p.y; s.z += p.z; s.w += p.w;
            }
            float4 sj = *(const float4*)&svec[j0];
            float si = svec[i];
            float c0 = invM * s.x - invM2 * si * sj.x;
            float c1 = invM * s.y - invM2 * si * sj.y;
            float c2 = invM * s.z - invM2 * si * sj.z;
            float c3 = invM * s.w - invM2 * si * sj.w;
            S0[i * LDP + j0 + 0] = c0;
            S0[i * LDP + j0 + 1] = c1;
            S0[i * LDP + j0 + 2] = c2;
            S0[i * LDP + j0 + 3] = c3;
            lsum += (c0 + c1) + (c2 + c3);
        }
#pragma unroll
        for (int o = 16; o; o >>= 1) lsum += __shfl_xor_sync(0xffffffffu, lsum, o);
        if ((t & 31) == 0) red[t >> 5] = lsum;
        __syncthreads();
        if (t == 0) { float s = 0.f; for (int q = 0; q < 8; q++) s += red[q]; snorm = s; }
        __syncthreads();

        const float invN = 1.f / snorm;
#pragma unroll
        for (int e = 0; e < 16; e++) {
            int idx = e * 256 + t;
            int i = idx >> 6, j = idx & 63;
            float a = S0[i * LDP + j] * invN;
            S0[i * LDP + j] = tf32f(a);
            float zy = 0.5f * (((i == j) ? 3.f : 0.f) - a);
            float zyt = tf32f(zy);
            S3[i * LDP + j] = zyt;   // ZY
            S2[i * LDP + j] = zyt;   // Z = ZY
        }
        __syncthreads();

        mm64t(S1, S0, S3, w, lane, 0);   // Y = A @ ZY

        float* pY = S1; float* pZ = S2; float* pT = S0; float* pU = S3;
        for (int it = 0; it < 3; it++) {
            mm64t(pT, pZ, pY, w, lane, 1);   // ZYnew = 0.5(3I - Z@Y)
            mm64t(pU, pY, pT, w, lane, 0);   // Ynew = Y @ ZYnew
            mm64t(pY, pT, pZ, w, lane, 0);   // Znew = ZYnew @ Z
            float* oY = pY; float* oZ = pZ; float* oT = pT; float* oU = pU;
            pY = oU; pZ = oY; pT = oT; pU = oZ;
        }

        // Stage conv center taps into the two dead smem matrices.
        float* W1 = pT;
        float* W2 = pU;
#pragma unroll
        for (int e = 0; e < 16; e++) {
            int n = e * 256 + t;
            W1[n] = w1[n * 9 + 4];
            W2[n] = w2[n * 9 + 4];
        }
        __syncthreads();
        // y_vec = (0.5/64)*sqrt(normA) * (3u - (u^T Z) Y), u = colsum(Y)
        if (t < 64) {
            float u = 0.f;
            for (int i = 0; i < 64; i++) u += pY[i * LDP + t];
            svec[t] = u;
        }
        __syncthreads();
        if (t < 64) {
            float vv = 0.f;
            for (int i = 0; i < 64; i++) vv += svec[i] * pZ[i * LDP + t];
            vvec[t] = vv;
        }
        __syncthreads();
        if (t < 64) {
            float wv = 0.f;
            for (int k = 0; k < 64; k++) wv += vvec[k] * pY[k * LDP + t];
            float cc = (0.5f / 64.f) * sqrtf(snorm);
            svec[t] = cc * (3.f * svec[t] - wv);
        }
        __syncthreads();
        if (t < 64) {
            float a = b1[t];
            for (int i = 0; i < 64; i++) a += W1[t * 64 + i] * svec[i];
            vvec[t] = fmaxf(a, 0.f);
        }
        __syncthreads();
        if (t < 64) {
            float a = b2[t];
            for (int i = 0; i < 64; i++) a += W2[t * 64 + i] * vvec[i];
            g_scale[b * 64 + t] = 1.f / (1.f + expf(-a));
        }
        __threadfence();
        __syncthreads();
        if (t == 0) atomicExch(&g_flag[b], 1);
    } else {
        // =================== scale block ===================
        const int s = blk - BATCH;
        const int start = s * SLICE;
        const int end = (start + SLICE < NF4) ? (start + SLICE) : NF4;
        if (start < end) {
            int bb0 = start >> 16, bb1 = (end - 1) >> 16;   // 65536 float4 per batch
            if (t == 0) {
                for (int bb = bb0; bb <= bb1; bb++)
                    while (atomicAdd(&g_flag[bb], 0) == 0) __nanosleep(100);
            }
            __syncthreads();
            __threadfence();
            const float4* x4 = (const float4*)x;
            float4* out4 = (float4*)out;
            for (int i = start + t; i < end; i += 256) {
                float sc = g_scale[i >> 10];   // 1024 float4 per channel
                float4 v = __ldg(&x4[i]);
                v.x *= sc; v.y *= sc; v.z *= sc; v.w *= sc;
                __stcs(&out4[i], v);
            }
        }
    }

    // Epilogue: globally-last block resets flags for the next graph replay.
    __threadfence();
    __syncthreads();
    if (t == 0) {
        if (atomicAdd(&g_done, 1) == (int)gridDim.x - 1) {
            for (int i = 0; i < BATCH; i++) atomicExch(&g_flag[i], 0);
            atomicExch(&g_done, 0);
        }
    }
}

extern "C" void kernel_launch(void* const* d_in, const int* in_sizes, int n_in,
                              void* d_out, int out_size) {
    const float* x  = (const float*)d_in[0];
    const float* w1 = (const float*)d_in[1];
    const float* b1 = (const float*)d_in[2];
    const float* w2 = (const float*)d_in[3];
    const float* b2 = (const float*)d_in[4];
    float* out = (float*)d_out;

    (void)in_sizes; (void)n_in; (void)out_size;

    cudaFuncSetAttribute(tail_kernel, cudaFuncAttributeMaxDynamicSharedMemorySize, DSMEM);

    dim3 gcov(NSPLIT, BATCH);
    cov_kernel<<<gcov, 256>>>(x);
    tail_kernel<<<BATCH + NSCALE, 256, DSMEM>>>(x, w1, b1, w2, b2, out);
}

// round 13
// speedup vs baseline: 1.9402x; 1.3542x over previous
#include <cuda_runtime.h>
#include <math.h>

#define BATCH  16
#define CC     64
#define MM     4096
#define NSPLIT 64     // one 64-col tile per block -> 1024 blocks
#define LDS    68     // smem row stride (words); 68 % 32 == 4 -> conflict-free frags
#define LDP    68

// Deterministic scratch (no float atomics)
__device__ float g_part[BATCH * NSPLIT * CC * CC];   // 16.8 MB partial Grams
__device__ float g_rspart[BATCH * NSPLIT * CC];
__device__ float g_cov[BATCH * CC * CC];
__device__ float g_scale[BATCH * CC];

__device__ __forceinline__ unsigned cvt_tf32(float f) {
    unsigned r; asm("cvt.rna.tf32.f32 %0, %1;" : "=r"(r) : "f"(f)); return r;
}
__device__ __forceinline__ float tf32f(float f) {
    return __uint_as_float(cvt_tf32(f));
}
__device__ __forceinline__ void mma_tf32(float c[4], unsigned a0, unsigned a1,
                                         unsigned a2, unsigned a3,
                                         unsigned b0, unsigned b1) {
    asm("mma.sync.aligned.m16n8k8.row.col.f32.tf32.tf32.f32 "
        "{%0,%1,%2,%3},{%4,%5,%6,%7},{%8,%9},{%0,%1,%2,%3};"
        : "+f"(c[0]), "+f"(c[1]), "+f"(c[2]), "+f"(c[3])
        : "r"(a0), "r"(a1), "r"(a2), "r"(a3), "r"(b0), "r"(b1));
}

// ---------------------------------------------------------------------------
// Kernel 1: partial X·X^T per (batch, 64-col tile) via tf32 mma.sync,
// + fp32 partial row sums. grid (NSPLIT, BATCH) = 1024 blocks, 256 threads.
// (R10-proven.)
// ---------------------------------------------------------------------------
__global__ __launch_bounds__(256) void cov_kernel(const float* __restrict__ x) {
    __shared__ unsigned buf[64 * LDS];
    const int split = blockIdx.x, b = blockIdx.y;
    const int t = threadIdx.x;
    const int lane = t & 31, w = t >> 5;
    const int m0 = 16 * (w & 3);
    const int n0base = 32 * (w >> 2);
    const int g = lane >> 2, tg = lane & 3;
    const int lrow = t >> 4, lcg = t & 15;
    const float* xb = x + (size_t)b * CC * MM + (size_t)split * 64;

    float4 v[4];
#pragma unroll
    for (int j = 0; j < 4; j++)
        v[j] = *(const float4*)&xb[(size_t)(j * 16 + lrow) * MM + 4 * lcg];

    float rs[4];
#pragma unroll
    for (int j = 0; j < 4; j++) {
        int row = j * 16 + lrow;
        rs[j] = (v[j].x + v[j].y) + (v[j].z + v[j].w);
        uint4 u;
        u.x = cvt_tf32(v[j].x); u.y = cvt_tf32(v[j].y);
        u.z = cvt_tf32(v[j].z); u.w = cvt_tf32(v[j].w);
        *(uint4*)&buf[row * LDS + 4 * lcg] = u;
    }
    __syncthreads();

    float c[4][4];
#pragma unroll
    for (int j = 0; j < 4; j++)
#pragma unroll
        for (int q = 0; q < 4; q++) c[j][q] = 0.f;

#pragma unroll
    for (int k0 = 0; k0 < 64; k0 += 8) {
        unsigned a0 = buf[(m0 + g) * LDS + k0 + tg];
        unsigned a1 = buf[(m0 + g + 8) * LDS + k0 + tg];
        unsigned a2 = buf[(m0 + g) * LDS + k0 + tg + 4];
        unsigned a3 = buf[(m0 + g + 8) * LDS + k0 + tg + 4];
#pragma unroll
        for (int j = 0; j < 4; j++) {
            int n0 = n0base + 8 * j;
            unsigned b0 = buf[(n0 + g) * LDS + k0 + tg];
            unsigned b1 = buf[(n0 + g) * LDS + k0 + tg + 4];
            mma_tf32(c[j], a0, a1, a2, a3, b0, b1);
        }
    }

    float* P = g_part + (((size_t)(b * NSPLIT + split)) << 12);
#pragma unroll
    for (int j = 0; j < 4; j++) {
        int row = m0 + g, col = n0base + 8 * j + 2 * tg;
        *(float2*)&P[row * 64 + col]       = make_float2(c[j][0], c[j][1]);
        *(float2*)&P[(row + 8) * 64 + col] = make_float2(c[j][2], c[j][3]);
    }

    __syncthreads();
    float* rsm = (float*)buf;
#pragma unroll
    for (int j = 0; j < 4; j++)
        rsm[(j * 16 + lrow) * 17 + lcg] = rs[j];
    __syncthreads();
    if (t < 64) {
        float s = 0.f;
#pragma unroll
        for (int i = 0; i < 16; i++) s += rsm[t * 17 + i];
        g_rspart[(b * NSPLIT + split) * 64 + t] = s;
    }
}

// ---------------------------------------------------------------------------
// Kernel 2: reduce partial Grams across splits (PDL: launches during cov).
// ---------------------------------------------------------------------------
__global__ __launch_bounds__(256) void reduce_kernel() {
#if __CUDA_ARCH__ >= 900
    cudaGridDependencySynchronize();
#endif
    int idx = blockIdx.x * 256 + threadIdx.x;       // 0 .. 16*4096-1
    int b = idx >> 12, e = idx & 4095;
    float s = 0.f;
#pragma unroll
    for (int sp = 0; sp < NSPLIT; sp++)
        s += g_part[(((size_t)(b * NSPLIT + sp)) << 12) + e];
    g_cov[idx] = s;
}

// ---------------------------------------------------------------------------
// 64x64x64 matmul via tf32 mma.sync on pre-rounded tf32-valued fp32 in smem.
// C = A@B (mode 0) or 0.5*(3I - A@B) (mode 1). Requires SYMMETRIC B.
// ---------------------------------------------------------------------------
__device__ __forceinline__ void mm64t(float* __restrict__ C, const float* __restrict__ A,
                                      const float* __restrict__ B, int w, int lane, int mode) {
    const int m0 = 16 * (w & 3);
    const int n0b = 32 * (w >> 2);
    const int g = lane >> 2, tg = lane & 3;
    const unsigned* Au = (const unsigned*)A;
    const unsigned* Bu = (const unsigned*)B;

    float c[4][4];
#pragma unroll
    for (int j = 0; j < 4; j++)
#pragma unroll
        for (int q = 0; q < 4; q++) c[j][q] = 0.f;

#pragma unroll
    for (int k0 = 0; k0 < 64; k0 += 8) {
        unsigned a0 = Au[(m0 + g) * LDP + k0 + tg];
        unsigned a1 = Au[(m0 + g + 8) * LDP + k0 + tg];
        unsigned a2 = Au[(m0 + g) * LDP + k0 + tg + 4];
        unsigned a3 = Au[(m0 + g + 8) * LDP + k0 + tg + 4];
#pragma unroll
        for (int j = 0; j < 4; j++) {
            int n0 = n0b + 8 * j;
            unsigned b0 = Bu[(n0 + g) * LDP + k0 + tg];
            unsigned b1 = Bu[(n0 + g) * LDP + k0 + tg + 4];
            mma_tf32(c[j], a0, a1, a2, a3, b0, b1);
        }
    }
    __syncthreads();
#pragma unroll
    for (int j = 0; j < 4; j++) {
        int col = n0b + 8 * j + 2 * tg;
        int r0 = m0 + g, r1 = m0 + g + 8;
        float v0 = c[j][0], v1 = c[j][1], v2 = c[j][2], v3 = c[j][3];
        if (mode) {
            v0 = 0.5f * (((r0 == col)     ? 3.f : 0.f) - v0);
            v1 = 0.5f * (((r0 == col + 1) ? 3.f : 0.f) - v1);
            v2 = 0.5f * (((r1 == col)     ? 3.f : 0.f) - v2);
            v3 = 0.5f * (((r1 == col + 1) ? 3.f : 0.f) - v3);
        }
        *(float2*)&C[r0 * LDP + col] = make_float2(tf32f(v0), tf32f(v1));
        *(float2*)&C[r1 * LDP + col] = make_float2(tf32f(v2), tf32f(v3));
    }
    __syncthreads();
}

// ---------------------------------------------------------------------------
// Kernel 3: covariance assembly + Newton-Schulz (tensor) + center-tap convs.
// 16 blocks x 256 threads. PDL: launches during reduce; conv taps are loaded
// before the grid sync (independent of reduce output).
// ---------------------------------------------------------------------------
__global__ __launch_bounds__(256) void ns_kernel(const float* __restrict__ w1, const float* __restrict__ b1,
                                                 const float* __restrict__ w2, const float* __restrict__ b2) {
    extern __shared__ float sm[];
    float* S0 = sm;
    float* S1 = sm + 64 * LDP;
    float* S2 = sm + 2 * 64 * LDP;
    float* S3 = sm + 3 * 64 * LDP;
    __shared__ float svec[64];
    __shared__ float vvec[64];
    __shared__ float red[8];
    __shared__ float snorm;

    const int b = blockIdx.x, t = threadIdx.x;
    const int lane = t & 31, w = t >> 5;
    const float invM = 1.0f / (float)MM;
    const float invM2 = invM * invM;

    // Prefix independent of predecessor: stage conv center taps into registers.
    float w1r[16], w2r[16];
#pragma unroll
    for (int e = 0; e < 16; e++) {
        int n = e * 256 + t;                 // n = outc*64 + inc
        w1r[e] = __ldg(&w1[n * 9 + 4]);
        w2r[e] = __ldg(&w2[n * 9 + 4]);
    }

#if __CUDA_ARCH__ >= 900
    cudaGridDependencySynchronize();
#endif

    // row sums (reduce split partials)
    if (t < 64) {
        float s = 0.f;
#pragma unroll
        for (int sp = 0; sp < NSPLIT; sp++) s += g_rspart[(b * NSPLIT + sp) * 64 + t];
        svec[t] = s;
    }
    __syncthreads();

    // cov = Sxx/M - s s^T / M^2 ; normA = sum(cov)
    float lsum = 0.f;
#pragma unroll
    for (int e = 0; e < 16; e++) {
        int idx = e * 256 + t;
        int i = idx >> 6, j = idx & 63;
        float cv = invM * g_cov[b * 4096 + idx] - invM2 * svec[i] * svec[j];
        S0[i * LDP + j] = cv;
        lsum += cv;
    }
#pragma unroll
    for (int o = 16; o; o >>= 1) lsum += __shfl_xor_sync(0xffffffffu, lsum, o);
    if ((t & 31) == 0) red[t >> 5] = lsum;
    __syncthreads();
    if (t == 0) { float s = 0.f; for (int q = 0; q < 8; q++) s += red[q]; snorm = s; }
    __syncthreads();

    const float invN = 1.f / snorm;
#pragma unroll
    for (int e = 0; e < 16; e++) {
        int idx = e * 256 + t;
        int i = idx >> 6, j = idx & 63;
        float a = S0[i * LDP + j] * invN;
        S0[i * LDP + j] = tf32f(a);
        float zy = 0.5f * (((i == j) ? 3.f : 0.f) - a);
        float zyt = tf32f(zy);
        S3[i * LDP + j] = zyt;   // ZY
        S2[i * LDP + j] = zyt;   // Z = ZY
    }
    __syncthreads();

    mm64t(S1, S0, S3, w, lane, 0);   // Y = A @ ZY

    float* pY = S1; float* pZ = S2; float* pT = S0; float* pU = S3;
    for (int it = 0; it < 3; it++) {
        mm64t(pT, pZ, pY, w, lane, 1);   // ZYnew = 0.5(3I - Z@Y)
        mm64t(pU, pY, pT, w, lane, 0);   // Ynew = Y @ ZYnew
        mm64t(pY, pT, pZ, w, lane, 0);   // Znew = ZYnew @ Z
        float* oY = pY; float* oZ = pZ; float* oT = pT; float* oU = pU;
        pY = oU; pZ = oY; pT = oT; pU = oZ;
    }

    // Spill staged conv taps into the two dead smem matrices.
    float* W1 = pT;
    float* W2 = pU;
#pragma unroll
    for (int e = 0; e < 16; e++) {
        int n = e * 256 + t;
        W1[n] = w1r[e];
        W2[n] = w2r[e];
    }
    __syncthreads();
    // y_vec = (0.5/64)*sqrt(normA) * (3u - (u^T Z) Y), u = colsum(Y)
    if (t < 64) {
        float u = 0.f;
        for (int i = 0; i < 64; i++) u += pY[i * LDP + t];
        svec[t] = u;
    }
    __syncthreads();
    if (t < 64) {
        float vv = 0.f;
        for (int i = 0; i < 64; i++) vv += svec[i] * pZ[i * LDP + t];
        vvec[t] = vv;
    }
    __syncthreads();
    if (t < 64) {
        float wv = 0.f;
        for (int k = 0; k < 64; k++) wv += vvec[k] * pY[k * LDP + t];
        float cc = (0.5f / 64.f) * sqrtf(snorm);
        svec[t] = cc * (3.f * svec[t] - wv);
    }
    __syncthreads();
    if (t < 64) {
        float a = b1[t];
        for (int i = 0; i < 64; i++) a += W1[t * 64 + i] * svec[i];
        vvec[t] = fmaxf(a, 0.f);
    }
    __syncthreads();
    if (t < 64) {
        float a = b2[t];
        for (int i = 0; i < 64; i++) a += W2[t * 64 + i] * vvec[i];
        g_scale[b * 64 + t] = 1.f / (1.f + expf(-a));
    }
}

// ---------------------------------------------------------------------------
// Kernel 4: out = scale[b,c] * x. PDL: launches during ns (which occupies only
// 16 SMs); ALL x loads are issued BEFORE the grid sync, so the read phase
// overlaps ns. After the sync, read g_scale and store.
// ---------------------------------------------------------------------------
__global__ __launch_bounds__(256) void scale_kernel(const float4* __restrict__ x4,
                                                    float4* __restrict__ out4) {
    int base = blockIdx.x * 2048 + threadIdx.x;
    float4 v[8];
#pragma unroll
    for (int j = 0; j < 8; j++)
        v[j] = __ldg(&x4[base + j * 256]);

#if __CUDA_ARCH__ >= 900
    cudaGridDependencySynchronize();
#endif

    float s[8];
#pragma unroll
    for (int j = 0; j < 8; j++)
        s[j] = g_scale[(base + j * 256) >> 10];   // 1024 float4 per (b,c)
#pragma unroll
    for (int j = 0; j < 8; j++) {
        int i = base + j * 256;
        float4 o = v[j];
        o.x *= s[j]; o.y *= s[j]; o.z *= s[j]; o.w *= s[j];
        __stcs(&out4[i], o);
    }
}

extern "C" void kernel_launch(void* const* d_in, const int* in_sizes, int n_in,
                              void* d_out, int out_size) {
    const float* x  = (const float*)d_in[0];
    const float* w1 = (const float*)d_in[1];
    const float* b1 = (const float*)d_in[2];
    const float* w2 = (const float*)d_in[3];
    const float* b2 = (const float*)d_in[4];
    float* out = (float*)d_out;

    (void)in_sizes; (void)n_in; (void)out_size;

    const int ns_smem = 4 * 64 * LDP * (int)sizeof(float);
    cudaFuncSetAttribute(ns_kernel, cudaFuncAttributeMaxDynamicSharedMemorySize, ns_smem);

    // PDL launch attribute: dependent kernel may launch while predecessor
    // drains; ordering enforced by cudaGridDependencySynchronize() in-kernel.
    cudaLaunchAttribute attr[1];
    attr[0].id = cudaLaunchAttributeProgrammaticStreamSerialization;
    attr[0].val.programmaticStreamSerializationAllowed = 1;

    dim3 gcov(NSPLIT, BATCH);
    cov_kernel<<<gcov, 256>>>(x);

    {
        cudaLaunchConfig_t cfg = {};
        cfg.gridDim = dim3(BATCH * CC * CC / 256);
        cfg.blockDim = dim3(256);
        cfg.attrs = attr; cfg.numAttrs = 1;
        cudaLaunchKernelEx(&cfg, reduce_kernel);
    }
    {
        cudaLaunchConfig_t cfg = {};
        cfg.gridDim = dim3(BATCH);
        cfg.blockDim = dim3(256);
        cfg.dynamicSmemBytes = ns_smem;
        cfg.attrs = attr; cfg.numAttrs = 1;
        cudaLaunchKernelEx(&cfg, ns_kernel, w1, b1, w2, b2);
    }
    {
        cudaLaunchConfig_t cfg = {};
        cfg.gridDim = dim3((BATCH * CC * MM / 4) / 2048);
        cfg.blockDim = dim3(256);
        cfg.attrs = attr; cfg.numAttrs = 1;
        cudaLaunchKernelEx(&cfg, scale_kernel, (const float4*)x, (float4*)out);
    }
}